// round 1
// baseline (speedup 1.0000x reference)
#include <cuda_runtime.h>

#define IN 448
#define OUT 224
#define NP 512          // 8*64 planes
#define EEW 240         // extended EE map width (offset 8)
#define OOW 224

// Scratch (static __device__ globals per the allocation rules)
__device__ float g_EE[(size_t)NP * EEW * EEW];   // ~118 MB
__device__ float g_OO[(size_t)NP * OOW * OOW];   // ~103 MB

__device__ __forceinline__ int refl(int i) {
    // numpy 'reflect': -1 -> 1, N -> N-2. Max excursion here is |i|<=16, i<=463.
    i = (i < 0) ? -i : i;
    return (i >= IN) ? (2 * IN - 2 - i) : i;
}

__device__ __forceinline__ float fmax4(float a, float b, float c, float d) {
    return fmaxf(fmaxf(a, b), fmaxf(c, d));
}

// ---------------------------------------------------------------------------
// Kernel 1: build half-resolution pair-max maps.
// EEext[y][x] (y,x in [-8,231], stored +8): max of input rows {2y,2y+1} x cols {2x,2x+1}, reflected.
// OO[y][x]   (y,x in [0,223]):              max of input rows {2y+1,2y+2} x cols {2x+1,2x+2}.
// ---------------------------------------------------------------------------
__global__ __launch_bounds__(256) void build_maps(const float* __restrict__ x) {
    int p   = blockIdx.y;
    int idx = blockIdx.x * 256 + threadIdx.x;
    const float* in = x + (size_t)p * IN * IN;

    if (idx < EEW * EEW) {
        int y  = idx / EEW, xx = idx % EEW;
        int yp = y - 8,     xp = xx - 8;
        int r0 = refl(2 * yp), r1 = refl(2 * yp + 1);
        float v;
        if (xp >= 0 && xp < OUT) {
            float2 a = *reinterpret_cast<const float2*>(in + (size_t)r0 * IN + 2 * xp);
            float2 b = *reinterpret_cast<const float2*>(in + (size_t)r1 * IN + 2 * xp);
            v = fmax4(a.x, a.y, b.x, b.y);
        } else {
            int c0 = refl(2 * xp), c1 = refl(2 * xp + 1);
            v = fmax4(in[(size_t)r0 * IN + c0], in[(size_t)r0 * IN + c1],
                      in[(size_t)r1 * IN + c0], in[(size_t)r1 * IN + c1]);
        }
        g_EE[(size_t)p * EEW * EEW + idx] = v;
    }

    if (idx < OOW * OOW) {
        int y = idx / OOW, xx = idx % OOW;
        int r0 = 2 * y + 1,  r1 = refl(2 * y + 2);
        int c0 = 2 * xx + 1, c1 = refl(2 * xx + 2);
        float v = fmax4(in[(size_t)r0 * IN + c0], in[(size_t)r0 * IN + c1],
                        in[(size_t)r1 * IN + c0], in[(size_t)r1 * IN + c1]);
        g_OO[(size_t)p * OOW * OOW + idx] = v;
    }
}

// ---------------------------------------------------------------------------
// Kernel 2: per 32x32 output tile, stage EE/OO tiles in smem, build 2D sparse
// tables (2x2 / 4x4 / 8x8 square maxes) conditionally on zones present, then
// answer each output pixel with <=4 corner lookups.
// ---------------------------------------------------------------------------

// dst[i][j] = max over {i,i+S} x {j,j+S} of src (src row width SRCN)
template <int SRCN, int DSTN, int S>
__device__ __forceinline__ void build_level(const float* __restrict__ src,
                                            float* __restrict__ dst, int tid) {
    for (int e = tid; e < DSTN * DSTN; e += 256) {
        int i = e / DSTN;
        int j = e - i * DSTN;
        const float* pp = src + i * SRCN + j;
        dst[e] = fmax4(pp[0], pp[S], pp[S * SRCN], pp[S * SRCN + S]);
    }
}

// smem layout (floats):
//  sEE  : 46*46 = 2116  @ 0
//  sS1E : 45*45 = 2025  @ 2116   (later reused as sOO 42*42 = 1764)
//  sS2E : 43*43 = 1849  @ 4141
//  sS3E : 39*39 = 1521  @ 5990
//  sS1O : 41*41 = 1681  @ 7511
//  sS2O : 39*39 = 1521  @ 9192
//  sS3O : 35*35 = 1225  @ 10713
//  total 11938 floats = 47752 B (< 48 KB static)
__global__ __launch_bounds__(256) void pool_kernel(float* __restrict__ out) {
    __shared__ float sm[11938];
    float* sEE  = sm;
    float* sS1E = sm + 2116;
    float* sOO  = sm + 2116;   // alias: S1E dead before OO is loaded
    float* sS2E = sm + 4141;
    float* sS3E = sm + 5990;
    float* sS1O = sm + 7511;
    float* sS2O = sm + 9192;
    float* sS3O = sm + 10713;

    const int p   = blockIdx.z;
    const int ty0 = blockIdx.y * 32;
    const int tx0 = blockIdx.x * 32;
    const int tid = threadIdx.x;

    // Zone flags from exact integer min/max radius over the tile
    int dyl = ty0 - 112, dyh = ty0 + 31 - 112;
    int dxl = tx0 - 112, dxh = tx0 + 31 - 112;
    int dymin = (dyl > 0) ? dyl : ((dyh < 0) ? -dyh : 0);
    int dxmin = (dxl > 0) ? dxl : ((dxh < 0) ? -dxh : 0);
    int dymax = max(abs(dyl), abs(dyh));
    int dxmax = max(abs(dxl), abs(dxh));
    int dmin2 = dymin * dymin + dxmin * dxmin;
    int dmax2 = dymax * dymax + dxmax * dxmax;

    bool hasK2  = (dmin2 < 3600);
    bool hasK8  = (dmin2 < 5625)  && (dmax2 >= 3600);
    bool hasK14 = (dmin2 < 8100)  && (dmax2 >= 5625);
    bool hasK20 = (dmin2 < 11025) && (dmax2 >= 8100);
    bool hasK26 = (dmax2 >= 11025);
    bool needEhi = hasK14 || hasK26;
    bool needE   = hasK2 || needEhi;
    bool needO   = hasK8 || hasK20;

    // Stage EE tile: sEE[i][j] = EEext[ty0-7+i][tx0-7+j]  (stored index +8)
    if (needE) {
        const float* EEp = g_EE + (size_t)p * EEW * EEW;
        for (int e = tid; e < 46 * 46; e += 256) {
            int i = e / 46, j = e - i * 46;
            sEE[e] = EEp[(size_t)(ty0 + 1 + i) * EEW + (tx0 + 1 + j)];
        }
    }
    __syncthreads();

    if (needEhi) {
        build_level<46, 45, 1>(sEE, sS1E, tid);
        __syncthreads();
        build_level<45, 43, 2>(sS1E, sS2E, tid);
        __syncthreads();
        if (hasK26) build_level<43, 39, 4>(sS2E, sS3E, tid);
    }
    __syncthreads();   // S1E dead from here; safe to overwrite with OO

    if (needO) {
        const float* OOp = g_OO + (size_t)p * OOW * OOW;
        const float NEG_INF = __int_as_float(0xff800000);
        for (int e = tid; e < 42 * 42; e += 256) {
            int i = e / 42, j = e - i * 42;
            int gy = ty0 - 5 + i, gx = tx0 - 5 + j;
            float v = NEG_INF;
            if (gy >= 0 && gy < OOW && gx >= 0 && gx < OOW)
                v = OOp[(size_t)gy * OOW + gx];
            sOO[e] = v;
        }
        __syncthreads();
        build_level<42, 41, 1>(sOO, sS1O, tid);
        __syncthreads();
        build_level<41, 39, 2>(sS1O, sS2O, tid);
        __syncthreads();
        if (hasK20) build_level<39, 35, 4>(sS2O, sS3O, tid);
    }
    __syncthreads();

    // Queries: 4 output pixels per thread
    #pragma unroll
    for (int q = 0; q < 4; q++) {
        int ry = (tid >> 5) + q * 8;
        int rx = tid & 31;
        int oy = ty0 + ry, ox = tx0 + rx;
        int dy = oy - 112, dx = ox - 112;
        int d2 = dy * dy + dx * dx;
        float v;
        if (d2 < 3600) {
            // k=2, m=1: single EE value
            v = sEE[(ry + 7) * 46 + (rx + 7)];
        } else if (d2 < 5625) {
            // k=8, m=4: exactly one S2O cell (4x4 aligned)
            v = sS2O[(ry + 3) * 39 + (rx + 3)];
        } else if (d2 < 8100) {
            // k=14, m=7: 4 corners of S2E (span 4), offset 3
            int i = ry + 4, j = rx + 4;
            v = fmax4(sS2E[i * 43 + j],        sS2E[i * 43 + j + 3],
                      sS2E[(i + 3) * 43 + j],  sS2E[(i + 3) * 43 + j + 3]);
        } else if (d2 < 11025) {
            // k=20, m=10: 4 corners of S3O (span 8), offset 2
            int i = ry, j = rx;
            v = fmax4(sS3O[i * 35 + j],        sS3O[i * 35 + j + 2],
                      sS3O[(i + 2) * 35 + j],  sS3O[(i + 2) * 35 + j + 2]);
        } else {
            // k=26, m=13: 4 corners of S3E (span 8), offset 5
            int i = ry + 1, j = rx + 1;
            v = fmax4(sS3E[i * 39 + j],        sS3E[i * 39 + j + 5],
                      sS3E[(i + 5) * 39 + j],  sS3E[(i + 5) * 39 + j + 5]);
        }
        out[((size_t)p * OUT + oy) * OUT + ox] = v;
    }
}

extern "C" void kernel_launch(void* const* d_in, const int* in_sizes, int n_in,
                              void* d_out, int out_size) {
    const float* x = (const float*)d_in[0];
    float* out = (float*)d_out;

    // Kernel 1: 240*240 = 57600 elems -> 225 blocks of 256, per plane
    build_maps<<<dim3(225, NP), 256>>>(x);
    // Kernel 2: 7x7 tiles of 32x32 outputs, per plane
    pool_kernel<<<dim3(7, 7, NP), 256>>>(out);
}

// round 2
// speedup vs baseline: 1.2480x; 1.2480x over previous
#include <cuda_runtime.h>

#define IN 448
#define OUT 224
#define NP 512          // 8*64 planes
#define EEW 240         // extended EE map width (offset 8)
#define OOW 224

// Scratch (static __device__ globals per the allocation rules)
__device__ float g_EE[(size_t)NP * EEW * EEW];   // ~118 MB
__device__ float g_OO[(size_t)NP * OOW * OOW];   // ~103 MB

__device__ __forceinline__ int refl(int i) {
    // numpy 'reflect': -1 -> 1, N -> N-2. Max excursion here is |i|<=16, i<=463.
    i = (i < 0) ? -i : i;
    return (i >= IN) ? (2 * IN - 2 - i) : i;
}

__device__ __forceinline__ float fmax4(float a, float b, float c, float d) {
    return fmaxf(fmaxf(a, b), fmaxf(c, d));
}

// ---------------------------------------------------------------------------
// Kernel 1: build half-resolution pair-max maps.
// EEext[y][x] (y,x in [-8,231], stored +8): max of input rows {2y,2y+1} x cols {2x,2x+1}, reflected.
// OO[y][x]   (y,x in [0,223]):              max of input rows {2y+1,2y+2} x cols {2x+1,2x+2}.
// ---------------------------------------------------------------------------
__global__ __launch_bounds__(256) void build_maps(const float* __restrict__ x) {
    int p   = blockIdx.y;
    int idx = blockIdx.x * 256 + threadIdx.x;
    const float* in = x + (size_t)p * IN * IN;

    if (idx < EEW * EEW) {
        int y  = idx / EEW, xx = idx % EEW;
        int yp = y - 8,     xp = xx - 8;
        int r0 = refl(2 * yp), r1 = refl(2 * yp + 1);
        float v;
        if (xp >= 0 && xp < OUT) {
            float2 a = *reinterpret_cast<const float2*>(in + (size_t)r0 * IN + 2 * xp);
            float2 b = *reinterpret_cast<const float2*>(in + (size_t)r1 * IN + 2 * xp);
            v = fmax4(a.x, a.y, b.x, b.y);
        } else {
            int c0 = refl(2 * xp), c1 = refl(2 * xp + 1);
            v = fmax4(in[(size_t)r0 * IN + c0], in[(size_t)r0 * IN + c1],
                      in[(size_t)r1 * IN + c0], in[(size_t)r1 * IN + c1]);
        }
        g_EE[(size_t)p * EEW * EEW + idx] = v;
    }

    if (idx < OOW * OOW) {
        int y = idx / OOW, xx = idx % OOW;
        int r0 = 2 * y + 1,  r1 = refl(2 * y + 2);
        int c0 = 2 * xx + 1, c1 = refl(2 * xx + 2);
        float v = fmax4(in[(size_t)r0 * IN + c0], in[(size_t)r0 * IN + c1],
                        in[(size_t)r1 * IN + c0], in[(size_t)r1 * IN + c1]);
        g_OO[(size_t)p * OOW * OOW + idx] = v;
    }
}

// ---------------------------------------------------------------------------
// Kernel 2: per 32x32 output tile, stage EE/OO tiles in smem, build 2D sparse
// tables (2x2 / 4x4 / 8x8 square maxes) conditionally on zones present, then
// answer each output pixel with <=4 corner lookups.
// 512 threads/block (16 warps): 4 blocks/SM x 512 = 2048 threads = full occ.
// All loops use division-free (warp, lane) 2D indexing.
// ---------------------------------------------------------------------------

// dst[i][j] = max over {i,i+S} x {j,j+S} of src (src row width SRCN)
template <int SRCN, int DSTN, int S>
__device__ __forceinline__ void build_level(const float* __restrict__ src,
                                            float* __restrict__ dst,
                                            int w, int l) {
    for (int i = w; i < DSTN; i += 16) {
        const float* r0 = src + i * SRCN;
        const float* r1 = r0 + S * SRCN;
        float* d = dst + i * DSTN;
        #pragma unroll
        for (int jb = 0; jb < DSTN; jb += 32) {
            int j = jb + l;
            if (j < DSTN)
                d[j] = fmax4(r0[j], r0[j + S], r1[j], r1[j + S]);
        }
    }
}

// smem layout (floats):
//  sEE  : 46*46 = 2116  @ 0
//  sS1E : 45*45 = 2025  @ 2116   (later reused as sOO 42*42 = 1764)
//  sS2E : 43*43 = 1849  @ 4141
//  sS3E : 39*39 = 1521  @ 5990
//  sS1O : 41*41 = 1681  @ 7511
//  sS2O : 39*39 = 1521  @ 9192
//  sS3O : 35*35 = 1225  @ 10713
//  total 11938 floats = 47752 B (< 48 KB static)
__global__ __launch_bounds__(512) void pool_kernel(float* __restrict__ out) {
    __shared__ float sm[11938];
    float* sEE  = sm;
    float* sS1E = sm + 2116;
    float* sOO  = sm + 2116;   // alias: S1E dead before OO is loaded
    float* sS2E = sm + 4141;
    float* sS3E = sm + 5990;
    float* sS1O = sm + 7511;
    float* sS2O = sm + 9192;
    float* sS3O = sm + 10713;

    const int p   = blockIdx.z;
    const int ty0 = blockIdx.y * 32;
    const int tx0 = blockIdx.x * 32;
    const int tid = threadIdx.x;
    const int w   = tid >> 5;   // warp 0..15
    const int l   = tid & 31;   // lane

    // Zone flags from exact integer min/max radius over the tile (block-uniform)
    int dyl = ty0 - 112, dyh = ty0 + 31 - 112;
    int dxl = tx0 - 112, dxh = tx0 + 31 - 112;
    int dymin = (dyl > 0) ? dyl : ((dyh < 0) ? -dyh : 0);
    int dxmin = (dxl > 0) ? dxl : ((dxh < 0) ? -dxh : 0);
    int dymax = max(abs(dyl), abs(dyh));
    int dxmax = max(abs(dxl), abs(dxh));
    int dmin2 = dymin * dymin + dxmin * dxmin;
    int dmax2 = dymax * dymax + dxmax * dxmax;

    bool hasK2  = (dmin2 < 3600);
    bool hasK8  = (dmin2 < 5625)  && (dmax2 >= 3600);
    bool hasK14 = (dmin2 < 8100)  && (dmax2 >= 5625);
    bool hasK20 = (dmin2 < 11025) && (dmax2 >= 8100);
    bool hasK26 = (dmax2 >= 11025);
    bool needEhi = hasK14 || hasK26;
    bool needE   = hasK2 || needEhi;
    bool needO   = hasK8 || hasK20;

    // Stage EE tile: sEE[i][j] = EEext[ty0-7+i][tx0-7+j]  (stored index +8)
    if (needE) {
        const float* EEp = g_EE + (size_t)p * EEW * EEW
                         + (size_t)(ty0 + 1) * EEW + (tx0 + 1);
        for (int i = w; i < 46; i += 16) {
            sEE[i * 46 + l] = EEp[(size_t)i * EEW + l];
            if (l < 14)
                sEE[i * 46 + 32 + l] = EEp[(size_t)i * EEW + 32 + l];
        }
    }
    __syncthreads();

    if (needEhi) {
        build_level<46, 45, 1>(sEE, sS1E, w, l);
        __syncthreads();
        build_level<45, 43, 2>(sS1E, sS2E, w, l);
        __syncthreads();
        if (hasK26) build_level<43, 39, 4>(sS2E, sS3E, w, l);
    }
    __syncthreads();   // S1E dead from here; safe to overwrite with OO

    if (needO) {
        const float* OOp = g_OO + (size_t)p * OOW * OOW;
        const float NEG_INF = __int_as_float(0xff800000);
        for (int i = w; i < 42; i += 16) {
            int gy = ty0 - 5 + i;
            bool okY = (gy >= 0) & (gy < OOW);
            #pragma unroll
            for (int jb = 0; jb < 42; jb += 32) {
                int j = jb + l;
                if (j < 42) {
                    int gx = tx0 - 5 + j;
                    float v = NEG_INF;
                    if (okY && gx >= 0 && gx < OOW)
                        v = OOp[(size_t)gy * OOW + gx];
                    sOO[i * 42 + j] = v;
                }
            }
        }
        __syncthreads();
        build_level<42, 41, 1>(sOO, sS1O, w, l);
        __syncthreads();
        build_level<41, 39, 2>(sS1O, sS2O, w, l);
        __syncthreads();
        if (hasK20) build_level<39, 35, 4>(sS2O, sS3O, w, l);
    }
    __syncthreads();

    // Queries: 2 output pixels per thread
    #pragma unroll
    for (int q = 0; q < 2; q++) {
        int ry = w + q * 16;
        int rx = l;
        int oy = ty0 + ry, ox = tx0 + rx;
        int dy = oy - 112, dx = ox - 112;
        int d2 = dy * dy + dx * dx;
        float v;
        if (d2 < 3600) {
            // k=2, m=1: single EE value
            v = sEE[(ry + 7) * 46 + (rx + 7)];
        } else if (d2 < 5625) {
            // k=8, m=4: exactly one S2O cell (4x4 aligned)
            v = sS2O[(ry + 3) * 39 + (rx + 3)];
        } else if (d2 < 8100) {
            // k=14, m=7: 4 corners of S2E (span 4), offset 3
            const float* b = sS2E + (ry + 4) * 43 + (rx + 4);
            v = fmax4(b[0], b[3], b[3 * 43], b[3 * 43 + 3]);
        } else if (d2 < 11025) {
            // k=20, m=10: 4 corners of S3O (span 8), offset 2
            const float* b = sS3O + ry * 35 + rx;
            v = fmax4(b[0], b[2], b[2 * 35], b[2 * 35 + 2]);
        } else {
            // k=26, m=13: 4 corners of S3E (span 8), offset 5
            const float* b = sS3E + (ry + 1) * 39 + (rx + 1);
            v = fmax4(b[0], b[5], b[5 * 39], b[5 * 39 + 5]);
        }
        out[((size_t)p * OUT + oy) * OUT + ox] = v;
    }
}

extern "C" void kernel_launch(void* const* d_in, const int* in_sizes, int n_in,
                              void* d_out, int out_size) {
    const float* x = (const float*)d_in[0];
    float* out = (float*)d_out;

    // Kernel 1: 240*240 = 57600 elems -> 225 blocks of 256, per plane
    build_maps<<<dim3(225, NP), 256>>>(x);
    // Kernel 2: 7x7 tiles of 32x32 outputs, per plane, 512 threads
    pool_kernel<<<dim3(7, 7, NP), 512>>>(out);
}

// round 3
// speedup vs baseline: 1.4391x; 1.1531x over previous
#include <cuda_runtime.h>

#define IN 448
#define OUT 224
#define NP 512          // 8*64 planes

__device__ __forceinline__ int refl(int i) {
    // numpy 'reflect': -1 -> 1, N -> N-2. Max excursion here |i|<=16, i<=463.
    i = (i < 0) ? -i : i;
    return (i >= IN) ? (2 * IN - 2 - i) : i;
}

__device__ __forceinline__ float fmax4(float a, float b, float c, float d) {
    return fmaxf(fmaxf(a, b), fmaxf(c, d));
}

// dst[i][j] = max over {i,i+S} x {j,j+S} of src (src row width SRCN)
template <int SRCN, int DSTN, int S>
__device__ __forceinline__ void build_level(const float* __restrict__ src,
                                            float* __restrict__ dst,
                                            int w, int l) {
    for (int i = w; i < DSTN; i += 16) {
        const float* r0 = src + i * SRCN;
        const float* r1 = r0 + S * SRCN;
        float* d = dst + i * DSTN;
        #pragma unroll
        for (int jb = 0; jb < DSTN; jb += 32) {
            int j = jb + l;
            if (j < DSTN)
                d[j] = fmax4(r0[j], r0[j + S], r1[j], r1[j + S]);
        }
    }
}

// ---------------------------------------------------------------------------
// Fully fused kernel: per 32x32 output tile, build half-res EE/OO pair-max
// tiles DIRECTLY from the input (reflect-padded), build sparse square-max
// tables in smem, answer each output pixel with <=4 lookups.
//
// EE[i][j] (i,j in 0..45) = max of input rows {2yp,2yp+1} cols {2xp,2xp+1},
//   yp=ty0-7+i, xp=tx0-7+j, reflected at borders.  Serves k in {2,14,26}.
// OO[i][j] (i,j in 0..41) = max of rows {2gy+1,2gy+2} cols {2gx+1,2gx+2},
//   gy=ty0-5+i, gx=tx0-5+j, valid only for gy,gx in [0,223] (else -inf).
//   Serves k in {8,20}.
//
// smem layout (floats):
//  sEE  : 46*46 = 2116  @ 0
//  sS1E : 45*45 = 2025  @ 2116   (later reused as sOO 42*42 = 1764)
//  sS2E : 43*43 = 1849  @ 4141
//  sS3E : 39*39 = 1521  @ 5990
//  sS1O : 41*41 = 1681  @ 7511
//  sS2O : 39*39 = 1521  @ 9192
//  sS3O : 35*35 = 1225  @ 10713
//  total 11938 floats = 47752 B -> 4 blocks/SM at 512 thr = full occupancy
// ---------------------------------------------------------------------------
__global__ __launch_bounds__(512, 4) void fused_pool(const float* __restrict__ x,
                                                     float* __restrict__ out) {
    __shared__ float sm[11938];
    float* sEE  = sm;
    float* sS1E = sm + 2116;
    float* sOO  = sm + 2116;   // alias: S1E dead before OO is stored
    float* sS2E = sm + 4141;
    float* sS3E = sm + 5990;
    float* sS1O = sm + 7511;
    float* sS2O = sm + 9192;
    float* sS3O = sm + 10713;

    const int p   = blockIdx.z;
    const int ty0 = blockIdx.y * 32;
    const int tx0 = blockIdx.x * 32;
    const int tid = threadIdx.x;
    const int w   = tid >> 5;   // warp 0..15
    const int l   = tid & 31;   // lane

    // Zone flags from exact integer min/max radius over the tile (block-uniform)
    int dyl = ty0 - 112, dyh = ty0 + 31 - 112;
    int dxl = tx0 - 112, dxh = tx0 + 31 - 112;
    int dymin = (dyl > 0) ? dyl : ((dyh < 0) ? -dyh : 0);
    int dxmin = (dxl > 0) ? dxl : ((dxh < 0) ? -dxh : 0);
    int dymax = max(abs(dyl), abs(dyh));
    int dxmax = max(abs(dxl), abs(dxh));
    int dmin2 = dymin * dymin + dxmin * dxmin;
    int dmax2 = dymax * dymax + dxmax * dxmax;

    bool hasK2  = (dmin2 < 3600);
    bool hasK8  = (dmin2 < 5625)  && (dmax2 >= 3600);
    bool hasK14 = (dmin2 < 8100)  && (dmax2 >= 5625);
    bool hasK20 = (dmin2 < 11025) && (dmax2 >= 8100);
    bool hasK26 = (dmax2 >= 11025);
    bool needEhi = hasK14 || hasK26;
    bool needE   = hasK2 || needEhi;
    bool needO   = hasK8 || hasK20;

    const float* in = x + (size_t)p * IN * IN;
    const float NEG_INF = __int_as_float(0xff800000);

    // ---- Prefetch OO values into registers (LDG latency hides behind E work)
    float vO[3][2];
    if (needO) {
        #pragma unroll
        for (int ii = 0; ii < 3; ii++) {
            int i  = w + 16 * ii;
            int gy = ty0 - 5 + i;
            bool okY = (i < 42) && ((unsigned)gy < (unsigned)OUT);
            int r0 = 2 * gy + 1;
            int r1 = (gy == 223) ? 446 : 2 * gy + 2;
            const float* R0 = in + (size_t)r0 * IN;
            const float* R1 = in + (size_t)r1 * IN;
            #pragma unroll
            for (int jb = 0; jb < 2; jb++) {
                int j  = jb * 32 + l;
                int gx = tx0 - 5 + j;
                float v = NEG_INF;
                if (okY && j < 42 && (unsigned)gx < (unsigned)OUT) {
                    int c0 = 2 * gx + 1;
                    int c1 = (gx == 223) ? 446 : 2 * gx + 2;
                    v = fmax4(R0[c0], R0[c1], R1[c0], R1[c1]);
                }
                vO[ii][jb] = v;
            }
        }
    }

    // ---- Build EE tile directly from input (with reflect at borders)
    if (needE) {
        for (int i = w; i < 46; i += 16) {
            int yp = ty0 - 7 + i;
            int r0, r1;
            if ((unsigned)yp < 224u) { r0 = 2 * yp; r1 = 2 * yp + 1; }
            else                     { r0 = refl(2 * yp); r1 = refl(2 * yp + 1); }
            const float* R0 = in + (size_t)r0 * IN;
            const float* R1 = in + (size_t)r1 * IN;
            #pragma unroll
            for (int jb = 0; jb < 2; jb++) {
                int j = jb * 32 + l;
                if (j < 46) {
                    int xp = tx0 - 7 + j;
                    float v;
                    if ((unsigned)xp < 224u) {
                        float2 a = *reinterpret_cast<const float2*>(R0 + 2 * xp);
                        float2 b = *reinterpret_cast<const float2*>(R1 + 2 * xp);
                        v = fmax4(a.x, a.y, b.x, b.y);
                    } else {
                        int c0 = refl(2 * xp), c1 = refl(2 * xp + 1);
                        v = fmax4(R0[c0], R0[c1], R1[c0], R1[c1]);
                    }
                    sEE[i * 46 + j] = v;
                }
            }
        }
    }
    __syncthreads();

    // ---- E pyramid (S1 2x2, S2 4x4, S3 8x8)
    if (needEhi) {
        build_level<46, 45, 1>(sEE, sS1E, w, l);
        __syncthreads();
        build_level<45, 43, 2>(sS1E, sS2E, w, l);
        __syncthreads();
        if (hasK26) build_level<43, 39, 4>(sS2E, sS3E, w, l);
    }
    __syncthreads();   // S1E fully consumed; safe to overwrite with OO

    // ---- Store prefetched OO, build O pyramid
    if (needO) {
        #pragma unroll
        for (int ii = 0; ii < 3; ii++) {
            int i = w + 16 * ii;
            if (i < 42) {
                sOO[i * 42 + l] = vO[ii][0];
                if (l < 10) sOO[i * 42 + 32 + l] = vO[ii][1];
            }
        }
        __syncthreads();
        build_level<42, 41, 1>(sOO, sS1O, w, l);
        __syncthreads();
        build_level<41, 39, 2>(sS1O, sS2O, w, l);
        __syncthreads();
        if (hasK20) build_level<39, 35, 4>(sS2O, sS3O, w, l);
    }
    __syncthreads();

    // ---- Queries: 2 output pixels per thread
    #pragma unroll
    for (int q = 0; q < 2; q++) {
        int ry = w + q * 16;
        int rx = l;
        int oy = ty0 + ry, ox = tx0 + rx;
        int dy = oy - 112, dx = ox - 112;
        int d2 = dy * dy + dx * dx;
        float v;
        if (d2 < 3600) {
            // k=2, m=1: single EE value
            v = sEE[(ry + 7) * 46 + (rx + 7)];
        } else if (d2 < 5625) {
            // k=8, m=4: exactly one S2O cell (4x4 aligned)
            v = sS2O[(ry + 3) * 39 + (rx + 3)];
        } else if (d2 < 8100) {
            // k=14, m=7: 4 corners of S2E (span 4), offset 3
            const float* b = sS2E + (ry + 4) * 43 + (rx + 4);
            v = fmax4(b[0], b[3], b[3 * 43], b[3 * 43 + 3]);
        } else if (d2 < 11025) {
            // k=20, m=10: 4 corners of S3O (span 8), offset 2
            const float* b = sS3O + ry * 35 + rx;
            v = fmax4(b[0], b[2], b[2 * 35], b[2 * 35 + 2]);
        } else {
            // k=26, m=13: 4 corners of S3E (span 8), offset 5
            const float* b = sS3E + (ry + 1) * 39 + (rx + 1);
            v = fmax4(b[0], b[5], b[5 * 39], b[5 * 39 + 5]);
        }
        out[((size_t)p * OUT + oy) * OUT + ox] = v;
    }
}

extern "C" void kernel_launch(void* const* d_in, const int* in_sizes, int n_in,
                              void* d_out, int out_size) {
    const float* x = (const float*)d_in[0];
    float* out = (float*)d_out;
    fused_pool<<<dim3(7, 7, NP), 512>>>(x, out);
}

// round 4
// speedup vs baseline: 1.6137x; 1.1213x over previous
#include <cuda_runtime.h>

#define IN 448
#define OUT 224
#define NP 512          // 8*64 planes

__device__ __forceinline__ int refl(int i) {
    // numpy 'reflect': -1 -> 1, N -> N-2. Max excursion here |i|<=16, i<=463.
    i = (i < 0) ? -i : i;
    return (i >= IN) ? (2 * IN - 2 - i) : i;
}

__device__ __forceinline__ float fmax4(float a, float b, float c, float d) {
    return fmaxf(fmaxf(a, b), fmaxf(c, d));
}

// ---------------------------------------------------------------------------
// Vectorized pyramid level: dst[i][j] = max over src{i,i+S}x{j,j+S}.
// Each lane computes output pair (j0, j0+1), j0 = 2*lane (float2 LDS/STS).
// Horizontal +S neighbor comes from lane l+S/2's registers via shuffle
// (for S=1 the odd column is a.y; only j0+2 needs the shuffle).
// DSTN is odd for every level, so the last pair's second element lands in a
// padding column that is never read -> boundary garbage is harmless.
// Idle lanes load clamped in-bounds addresses so shuffles stay converged.
// ---------------------------------------------------------------------------
template <int SRCP, int DSTP, int DSTN, int S>
__device__ __forceinline__ void build_level(const float* __restrict__ src,
                                            float* __restrict__ dst,
                                            int w, int l) {
    constexpr int NPAIR = (DSTN + 1) / 2;
    constexpr unsigned FULL = 0xffffffffu;
    const int j0 = min(2 * l, SRCP - 2);
    const bool on = (l < NPAIR);
    #pragma unroll
    for (int ii = 0; ii < 3; ii++) {
        int i = w + 16 * ii;
        if (ii < 2 || i < DSTN) {           // warp-uniform guard
            float2 a0 = *reinterpret_cast<const float2*>(src + i * SRCP + j0);
            float2 a1 = *reinterpret_cast<const float2*>(src + (i + S) * SRCP + j0);
            float mx = fmaxf(a0.x, a1.x);
            float my = fmaxf(a0.y, a1.y);
            float o0, o1;
            if (S == 1) {
                float nb = __shfl_down_sync(FULL, mx, 1);   // col j0+2
                o0 = fmaxf(mx, my);
                o1 = fmaxf(my, nb);
            } else {
                float bx = __shfl_down_sync(FULL, mx, S / 2);  // col j0+S
                float by = __shfl_down_sync(FULL, my, S / 2);  // col j0+S+1
                o0 = fmaxf(mx, bx);
                o1 = fmaxf(my, by);
            }
            if (on)
                *reinterpret_cast<float2*>(dst + i * DSTP + 2 * l) =
                    make_float2(o0, o1);
        }
    }
}

// ---------------------------------------------------------------------------
// Fully fused kernel. smem layout (floats, all base offsets 8B-aligned):
//  sEE  : 46 rows x pitch 46 = 2116 @ 0      (valid cols 0..45)
//  sS1E : 45 x 46 = 2070 @ 2116              (valid 0..44, col 45 pad)
//  sOO  : 42 x 42 = 1764 @ 2116  (alias; S1E dead before OO stored)
//  sS2E : 43 x 44 = 1892 @ 4186              (valid 0..42, col 43 pad)
//  sS3E : 39 x 40 = 1560 @ 6078              (valid 0..38, col 39 pad)
//  sS1O : 41 x 42 = 1722 @ 7638              (valid 0..40, col 41 pad)
//  sS2O : 39 x 40 = 1560 @ 9360              (valid 0..38, col 39 pad)
//  sS3O : 35 x 36 = 1260 @ 10920             (valid 0..34, col 35 pad)
//  total 12180 floats = 48720 B  -> 4 blocks/SM @ 512 thr = full occupancy
// ---------------------------------------------------------------------------
__global__ __launch_bounds__(512, 4) void fused_pool(const float* __restrict__ x,
                                                     float* __restrict__ out) {
    __shared__ __align__(16) float sm[12180];
    float* sEE  = sm;
    float* sS1E = sm + 2116;
    float* sOO  = sm + 2116;
    float* sS2E = sm + 4186;
    float* sS3E = sm + 6078;
    float* sS1O = sm + 7638;
    float* sS2O = sm + 9360;
    float* sS3O = sm + 10920;

    const int p   = blockIdx.z;
    const int ty0 = blockIdx.y * 32;
    const int tx0 = blockIdx.x * 32;
    const int tid = threadIdx.x;
    const int w   = tid >> 5;
    const int l   = tid & 31;

    // Zone flags (block-uniform, exact integer min/max radius)
    int dyl = ty0 - 112, dyh = ty0 + 31 - 112;
    int dxl = tx0 - 112, dxh = tx0 + 31 - 112;
    int dymin = (dyl > 0) ? dyl : ((dyh < 0) ? -dyh : 0);
    int dxmin = (dxl > 0) ? dxl : ((dxh < 0) ? -dxh : 0);
    int dymax = max(abs(dyl), abs(dyh));
    int dxmax = max(abs(dxl), abs(dxh));
    int dmin2 = dymin * dymin + dxmin * dxmin;
    int dmax2 = dymax * dymax + dxmax * dxmax;

    bool hasK2  = (dmin2 < 3600);
    bool hasK8  = (dmin2 < 5625)  && (dmax2 >= 3600);
    bool hasK14 = (dmin2 < 8100)  && (dmax2 >= 5625);
    bool hasK20 = (dmin2 < 11025) && (dmax2 >= 8100);
    bool hasK26 = (dmax2 >= 11025);
    bool needEhi = hasK14 || hasK26;
    bool needE   = hasK2 || needEhi;
    bool needO   = hasK8 || hasK20;

    const float* in = x + (size_t)p * IN * IN;
    const float NEG_INF = __int_as_float(0xff800000);

    // ---- Stage EE: sEE[i][j] = max of input rows {2yp,2yp+1} cols {2xp,2xp+1}
    //      yp = ty0-7+i, xp = tx0-7+j, reflected at borders. Pair per lane.
    if (needE && l < 23) {
        const int j0 = 2 * l;
        #pragma unroll
        for (int ii = 0; ii < 3; ii++) {
            int i = w + 16 * ii;
            if (ii < 2 || i < 46) {
                int yp = ty0 - 7 + i;
                int r0, r1;
                if ((unsigned)yp < 224u) { r0 = 2 * yp; r1 = 2 * yp + 1; }
                else                     { r0 = refl(2 * yp); r1 = refl(2 * yp + 1); }
                const float* R0 = in + (size_t)r0 * IN;
                const float* R1 = in + (size_t)r1 * IN;
                int xp0 = tx0 - 7 + j0;
                float v0, v1;
                if ((unsigned)xp0 < 223u) {   // xp0, xp0+1 both interior
                    float2 a = *reinterpret_cast<const float2*>(R0 + 2 * xp0);
                    float2 b = *reinterpret_cast<const float2*>(R0 + 2 * xp0 + 2);
                    float2 c = *reinterpret_cast<const float2*>(R1 + 2 * xp0);
                    float2 d = *reinterpret_cast<const float2*>(R1 + 2 * xp0 + 2);
                    v0 = fmax4(a.x, a.y, c.x, c.y);
                    v1 = fmax4(b.x, b.y, d.x, d.y);
                } else {
                    int c0 = refl(2 * xp0),     c1 = refl(2 * xp0 + 1);
                    v0 = fmax4(R0[c0], R0[c1], R1[c0], R1[c1]);
                    int c2 = refl(2 * xp0 + 2), c3 = refl(2 * xp0 + 3);
                    v1 = fmax4(R0[c2], R0[c3], R1[c2], R1[c3]);
                }
                *reinterpret_cast<float2*>(sEE + i * 46 + j0) = make_float2(v0, v1);
            }
        }
    }
    __syncthreads();

    // ---- E pyramid
    if (needEhi) {
        build_level<46, 46, 45, 1>(sEE, sS1E, w, l);
        __syncthreads();
        build_level<46, 44, 43, 2>(sS1E, sS2E, w, l);
        __syncthreads();
        if (hasK26) build_level<44, 40, 39, 4>(sS2E, sS3E, w, l);
    }
    __syncthreads();   // S1E fully consumed; safe to overwrite with OO

    // ---- Stage OO: sOO[i][j] = max of rows {2gy+1,2gy+2} cols {2gx+1,2gx+2}
    //      gy = ty0-5+i, gx = tx0-5+j; -inf outside [0,223]. Pair per lane.
    if (needO && l < 21) {
        const int j0 = 2 * l;
        #pragma unroll
        for (int ii = 0; ii < 3; ii++) {
            int i = w + 16 * ii;
            if (ii < 2 || i < 42) {
                int gy = ty0 - 5 + i;
                float v0 = NEG_INF, v1 = NEG_INF;
                if ((unsigned)gy < 224u) {
                    int r0 = 2 * gy + 1;
                    int r1 = (gy == 223) ? 446 : 2 * gy + 2;
                    const float* R0 = in + (size_t)r0 * IN;
                    const float* R1 = in + (size_t)r1 * IN;
                    int gx0 = tx0 - 5 + j0;
                    if ((unsigned)gx0 <= 221u) {
                        // cols 2gx0+1 .. 2gx0+4 : scalar, f2, scalar per row
                        float  a0 = R0[2 * gx0 + 1], a3 = R0[2 * gx0 + 4];
                        float2 am = *reinterpret_cast<const float2*>(R0 + 2 * gx0 + 2);
                        float  b0 = R1[2 * gx0 + 1], b3 = R1[2 * gx0 + 4];
                        float2 bm = *reinterpret_cast<const float2*>(R1 + 2 * gx0 + 2);
                        v0 = fmax4(a0, am.x, b0, bm.x);
                        v1 = fmax4(am.y, a3, bm.y, b3);
                    } else {
                        if ((unsigned)gx0 < 224u) {
                            int c0 = 2 * gx0 + 1;
                            int c1 = (gx0 == 223) ? 446 : 2 * gx0 + 2;
                            v0 = fmax4(R0[c0], R0[c1], R1[c0], R1[c1]);
                        }
                        int gx1 = gx0 + 1;
                        if ((unsigned)gx1 < 224u) {
                            int c0 = 2 * gx1 + 1;
                            int c1 = (gx1 == 223) ? 446 : 2 * gx1 + 2;
                            v1 = fmax4(R0[c0], R0[c1], R1[c0], R1[c1]);
                        }
                    }
                }
                *reinterpret_cast<float2*>(sOO + i * 42 + j0) = make_float2(v0, v1);
            }
        }
    }
    __syncthreads();

    // ---- O pyramid
    if (needO) {
        build_level<42, 42, 41, 1>(sOO, sS1O, w, l);
        __syncthreads();
        build_level<42, 40, 39, 2>(sS1O, sS2O, w, l);
        __syncthreads();
        if (hasK20) build_level<40, 36, 35, 4>(sS2O, sS3O, w, l);
    }
    __syncthreads();

    // ---- Queries: 2 output pixels per thread
    #pragma unroll
    for (int q = 0; q < 2; q++) {
        int ry = w + q * 16;
        int rx = l;
        int oy = ty0 + ry, ox = tx0 + rx;
        int dy = oy - 112, dx = ox - 112;
        int d2 = dy * dy + dx * dx;
        float v;
        if (d2 < 3600) {
            // k=2, m=1: single EE value
            v = sEE[(ry + 7) * 46 + (rx + 7)];
        } else if (d2 < 5625) {
            // k=8, m=4: exactly one S2O cell (4x4 aligned)
            v = sS2O[(ry + 3) * 40 + (rx + 3)];
        } else if (d2 < 8100) {
            // k=14, m=7: 4 corners of S2E (span 4), offset 3
            const float* b = sS2E + (ry + 4) * 44 + (rx + 4);
            v = fmax4(b[0], b[3], b[3 * 44], b[3 * 44 + 3]);
        } else if (d2 < 11025) {
            // k=20, m=10: 4 corners of S3O (span 8), offset 2
            const float* b = sS3O + ry * 36 + rx;
            v = fmax4(b[0], b[2], b[2 * 36], b[2 * 36 + 2]);
        } else {
            // k=26, m=13: 4 corners of S3E (span 8), offset 5
            const float* b = sS3E + (ry + 1) * 40 + (rx + 1);
            v = fmax4(b[0], b[5], b[5 * 40], b[5 * 40 + 5]);
        }
        out[((size_t)p * OUT + oy) * OUT + ox] = v;
    }
}

extern "C" void kernel_launch(void* const* d_in, const int* in_sizes, int n_in,
                              void* d_out, int out_size) {
    const float* x = (const float*)d_in[0];
    float* out = (float*)d_out;
    fused_pool<<<dim3(7, 7, NP), 512>>>(x, out);
}

// round 5
// speedup vs baseline: 1.7501x; 1.0845x over previous
#include <cuda_runtime.h>

#define IN 448
#define OUT 224
#define NP 512          // 8*64 planes
#define FULLM 0xffffffffu

__device__ __forceinline__ int refl(int i) {
    i = (i < 0) ? -i : i;
    return (i >= IN) ? (2 * IN - 2 - i) : i;
}

__device__ __forceinline__ float fmax4(float a, float b, float c, float d) {
    return fmaxf(fmaxf(a, b), fmaxf(c, d));
}

// ---------------------------------------------------------------------------
// S2 level directly from base: dst[i][j] = max src[i..i+3][j..j+3].
// Lane pair (j0,j0+1), j0=2l. Vertical max of 4 rows in regs, horizontal
// window of 4 via 3 shuffles. DSTN odd -> last pair's 2nd elem is padding.
// ---------------------------------------------------------------------------
template <int SRCP, int DSTP, int DSTN>
__device__ __forceinline__ void build_s2(const float* __restrict__ src,
                                         float* __restrict__ dst,
                                         int w, int l, int lo, int hi) {
    constexpr int NPAIR = (DSTN + 1) / 2;
    const int j0 = min(2 * l, SRCP - 2);
    const bool on = (l < NPAIR);
    for (int i = lo + w; i <= hi; i += 16) {
        const float* s = src + i * SRCP + j0;
        float2 a = *reinterpret_cast<const float2*>(s);
        float2 b = *reinterpret_cast<const float2*>(s + SRCP);
        float2 c = *reinterpret_cast<const float2*>(s + 2 * SRCP);
        float2 d = *reinterpret_cast<const float2*>(s + 3 * SRCP);
        float mx = fmax4(a.x, b.x, c.x, d.x);
        float my = fmax4(a.y, b.y, c.y, d.y);
        float nx  = __shfl_down_sync(FULLM, mx, 1);   // col j0+2
        float ny  = __shfl_down_sync(FULLM, my, 1);   // col j0+3
        float mmx = __shfl_down_sync(FULLM, mx, 2);   // col j0+4
        float o0 = fmax4(mx, my, nx, ny);
        float o1 = fmax4(my, nx, ny, mmx);
        if (on)
            *reinterpret_cast<float2*>(dst + i * DSTP + 2 * l) = make_float2(o0, o1);
    }
}

// S3 from S2 (span 4): dst[i][j] = max src{i,i+4}x{j,j+4}
template <int SRCP, int DSTP, int DSTN>
__device__ __forceinline__ void build_s4(const float* __restrict__ src,
                                         float* __restrict__ dst,
                                         int w, int l, int lo, int hi) {
    constexpr int NPAIR = (DSTN + 1) / 2;
    const int j0 = min(2 * l, SRCP - 2);
    const bool on = (l < NPAIR);
    for (int i = lo + w; i <= hi; i += 16) {
        float2 a = *reinterpret_cast<const float2*>(src + i * SRCP + j0);
        float2 b = *reinterpret_cast<const float2*>(src + (i + 4) * SRCP + j0);
        float mx = fmaxf(a.x, b.x);
        float my = fmaxf(a.y, b.y);
        float bx = __shfl_down_sync(FULLM, mx, 2);    // col j0+4
        float by = __shfl_down_sync(FULLM, my, 2);    // col j0+5
        float o0 = fmaxf(mx, bx);
        float o1 = fmaxf(my, by);
        if (on)
            *reinterpret_cast<float2*>(dst + i * DSTP + 2 * l) = make_float2(o0, o1);
    }
}

// ---------------------------------------------------------------------------
// smem layout (floats):
//  sEE  : 46 x 46 = 2116 @ 0      (valid cols 0..45)
//  sS2E : 43 x 44 = 1892 @ 2116   (valid 0..42, col 43 pad)
//  sS3E : 39 x 40 = 1560 @ 4008   (valid 0..38, col 39 pad)
//  sOO  : 42 x 42 = 1764 @ 5568   (valid 0..41)
//  sS2O : 39 x 40 = 1560 @ 7332   (valid 0..38, col 39 pad)
//  sS3O : 35 x 36 = 1260 @ 8892   (valid 0..34, col 35 pad)
//  total 10152 floats = 40608 B -> 4 blocks/SM @ 512 thr
// ---------------------------------------------------------------------------
__global__ __launch_bounds__(512, 4) void fused_pool(const float* __restrict__ x,
                                                     float* __restrict__ out) {
    __shared__ __align__(16) float sm[10152];
    float* sEE  = sm;
    float* sS2E = sm + 2116;
    float* sS3E = sm + 4008;
    float* sOO  = sm + 5568;
    float* sS2O = sm + 7332;
    float* sS3O = sm + 8892;

    const int p   = blockIdx.z;
    const int ty0 = blockIdx.y * 32;
    const int tx0 = blockIdx.x * 32;
    const int tid = threadIdx.x;
    const int w   = tid >> 5;
    const int l   = tid & 31;

    // Column extremes of |dx| over this tile (block-uniform)
    int dxl = tx0 - 112, dxh = tx0 + 31 - 112;
    int dxmin = (dxl > 0) ? dxl : ((dxh < 0) ? -dxh : 0);
    int dxmax = max(abs(dxl), abs(dxh));
    int dxmin2 = dxmin * dxmin, dxmax2 = dxmax * dxmax;

    // Per-zone row ranges via one ballot per zone (lane = tile row)
    int l2 = 127, h2 = -1, l8 = 127, h8 = -1, l14 = 127, h14 = -1;
    int l20 = 127, h20 = -1, l26 = 127, h26 = -1;
    {
        int dy  = ty0 + l - 112;
        int rm2 = dy * dy + dxmin2;   // min d2 in this row
        int rM2 = dy * dy + dxmax2;   // max d2 in this row
        unsigned m;
        m = __ballot_sync(FULLM, rm2 < 3600);
        if (m) { l2  = __ffs(m) - 1; h2  = 31 - __clz(m); }
        m = __ballot_sync(FULLM, rm2 < 5625  && rM2 >= 3600);
        if (m) { l8  = __ffs(m) - 1; h8  = 31 - __clz(m); }
        m = __ballot_sync(FULLM, rm2 < 8100  && rM2 >= 5625);
        if (m) { l14 = __ffs(m) - 1; h14 = 31 - __clz(m); }
        m = __ballot_sync(FULLM, rm2 < 11025 && rM2 >= 8100);
        if (m) { l20 = __ffs(m) - 1; h20 = 31 - __clz(m); }
        m = __ballot_sync(FULLM, rM2 >= 11025);
        if (m) { l26 = __ffs(m) - 1; h26 = 31 - __clz(m); }
    }

    // Producer row ranges from consumer needs
    int s3eLo = 127, s3eHi = -1;
    if (h26 >= 0) { s3eLo = l26 + 1; s3eHi = h26 + 6; }
    int s2eLo = 127, s2eHi = -1;
    if (h14 >= 0) { s2eLo = l14 + 4; s2eHi = h14 + 7; }
    if (s3eHi >= 0) { s2eLo = min(s2eLo, s3eLo); s2eHi = max(s2eHi, s3eHi + 4); }
    s2eHi = min(s2eHi, 42);
    int eeLo = 127, eeHi = -1;
    if (h2 >= 0) { eeLo = l2 + 7; eeHi = h2 + 7; }
    if (s2eHi >= 0) { eeLo = min(eeLo, s2eLo); eeHi = max(eeHi, s2eHi + 3); }
    eeHi = min(eeHi, 45);
    s3eHi = min(s3eHi, 38);

    int s3oLo = 127, s3oHi = -1;
    if (h20 >= 0) { s3oLo = l20; s3oHi = h20 + 2; }
    int s2oLo = 127, s2oHi = -1;
    if (h8 >= 0) { s2oLo = l8 + 3; s2oHi = h8 + 3; }
    if (s3oHi >= 0) { s2oLo = min(s2oLo, s3oLo); s2oHi = max(s2oHi, s3oHi + 4); }
    s2oHi = min(s2oHi, 38);
    int ooLo = 127, ooHi = -1;
    if (s2oHi >= 0) { ooLo = s2oLo; ooHi = min(s2oHi + 3, 41); }
    s3oHi = min(s3oHi, 34);

    const float* in = x + (size_t)p * IN * IN;
    const float NEG_INF = __int_as_float(0xff800000);

    // ---- Stage EE rows [eeLo, eeHi]:
    //   sEE[i][j] = max input rows {2yp,2yp+1} cols {2xp,2xp+1},
    //   yp = ty0-7+i, xp = tx0-7+j, reflected. Pair per lane.
    if (l < 23) {
        const int j0 = 2 * l;
        for (int i = eeLo + w; i <= eeHi; i += 16) {
            int yp = ty0 - 7 + i;
            int r0, r1;
            if ((unsigned)yp < 224u) { r0 = 2 * yp; r1 = 2 * yp + 1; }
            else                     { r0 = refl(2 * yp); r1 = refl(2 * yp + 1); }
            const float* R0 = in + (size_t)r0 * IN;
            const float* R1 = in + (size_t)r1 * IN;
            int xp0 = tx0 - 7 + j0;
            float v0, v1;
            if ((unsigned)xp0 < 223u) {
                float2 a = *reinterpret_cast<const float2*>(R0 + 2 * xp0);
                float2 b = *reinterpret_cast<const float2*>(R0 + 2 * xp0 + 2);
                float2 c = *reinterpret_cast<const float2*>(R1 + 2 * xp0);
                float2 d = *reinterpret_cast<const float2*>(R1 + 2 * xp0 + 2);
                v0 = fmax4(a.x, a.y, c.x, c.y);
                v1 = fmax4(b.x, b.y, d.x, d.y);
            } else {
                int c0 = refl(2 * xp0),     c1 = refl(2 * xp0 + 1);
                v0 = fmax4(R0[c0], R0[c1], R1[c0], R1[c1]);
                int c2 = refl(2 * xp0 + 2), c3 = refl(2 * xp0 + 3);
                v1 = fmax4(R0[c2], R0[c3], R1[c2], R1[c3]);
            }
            *reinterpret_cast<float2*>(sEE + i * 46 + j0) = make_float2(v0, v1);
        }
    }

    // ---- Stage OO rows [ooLo, ooHi]:
    //   sOO[i][j] = max rows {2gy+1,2gy+2} cols {2gx+1,2gx+2},
    //   gy = ty0-5+i, gx = tx0-5+j; -inf outside [0,223].
    if (l < 21) {
        const int j0 = 2 * l;
        for (int i = ooLo + w; i <= ooHi; i += 16) {
            int gy = ty0 - 5 + i;
            float v0 = NEG_INF, v1 = NEG_INF;
            if ((unsigned)gy < 224u) {
                int r0 = 2 * gy + 1;
                int r1 = (gy == 223) ? 446 : 2 * gy + 2;
                const float* R0 = in + (size_t)r0 * IN;
                const float* R1 = in + (size_t)r1 * IN;
                int gx0 = tx0 - 5 + j0;
                if ((unsigned)gx0 <= 221u) {
                    float  a0 = R0[2 * gx0 + 1], a3 = R0[2 * gx0 + 4];
                    float2 am = *reinterpret_cast<const float2*>(R0 + 2 * gx0 + 2);
                    float  b0 = R1[2 * gx0 + 1], b3 = R1[2 * gx0 + 4];
                    float2 bm = *reinterpret_cast<const float2*>(R1 + 2 * gx0 + 2);
                    v0 = fmax4(a0, am.x, b0, bm.x);
                    v1 = fmax4(am.y, a3, bm.y, b3);
                } else {
                    if ((unsigned)gx0 < 224u) {
                        int c0 = 2 * gx0 + 1;
                        int c1 = (gx0 == 223) ? 446 : 2 * gx0 + 2;
                        v0 = fmax4(R0[c0], R0[c1], R1[c0], R1[c1]);
                    }
                    int gx1 = gx0 + 1;
                    if ((unsigned)gx1 < 224u) {
                        int c0 = 2 * gx1 + 1;
                        int c1 = (gx1 == 223) ? 446 : 2 * gx1 + 2;
                        v1 = fmax4(R0[c0], R0[c1], R1[c0], R1[c1]);
                    }
                }
            }
            *reinterpret_cast<float2*>(sOO + i * 42 + j0) = make_float2(v0, v1);
        }
    }
    __syncthreads();

    // ---- Level-2 tables (4x4 windows), restricted rows
    build_s2<46, 44, 43>(sEE, sS2E, w, l, s2eLo, s2eHi);
    build_s2<42, 40, 39>(sOO, sS2O, w, l, s2oLo, s2oHi);
    __syncthreads();

    // ---- Level-3 tables (8x8 windows), restricted rows
    build_s4<44, 40, 39>(sS2E, sS3E, w, l, s3eLo, s3eHi);
    build_s4<40, 36, 35>(sS2O, sS3O, w, l, s3oLo, s3oHi);
    __syncthreads();

    // ---- Queries: 2 output pixels per thread
    #pragma unroll
    for (int q = 0; q < 2; q++) {
        int ry = w + q * 16;
        int rx = l;
        int oy = ty0 + ry, ox = tx0 + rx;
        int dy = oy - 112, dx = ox - 112;
        int d2 = dy * dy + dx * dx;
        float v;
        if (d2 < 3600) {
            v = sEE[(ry + 7) * 46 + (rx + 7)];                       // k=2
        } else if (d2 < 5625) {
            v = sS2O[(ry + 3) * 40 + (rx + 3)];                      // k=8
        } else if (d2 < 8100) {
            const float* b = sS2E + (ry + 4) * 44 + (rx + 4);        // k=14
            v = fmax4(b[0], b[3], b[3 * 44], b[3 * 44 + 3]);
        } else if (d2 < 11025) {
            const float* b = sS3O + ry * 36 + rx;                    // k=20
            v = fmax4(b[0], b[2], b[2 * 36], b[2 * 36 + 2]);
        } else {
            const float* b = sS3E + (ry + 1) * 40 + (rx + 1);        // k=26
            v = fmax4(b[0], b[5], b[5 * 40], b[5 * 40 + 5]);
        }
        out[((size_t)p * OUT + oy) * OUT + ox] = v;
    }
}

extern "C" void kernel_launch(void* const* d_in, const int* in_sizes, int n_in,
                              void* d_out, int out_size) {
    const float* x = (const float*)d_in[0];
    float* out = (float*)d_out;
    fused_pool<<<dim3(7, 7, NP), 512>>>(x, out);
}

// round 6
// speedup vs baseline: 1.9857x; 1.1346x over previous
#include <cuda_runtime.h>

#define IN 448
#define OUT 224
#define NP 512          // 8*64 planes
#define FULLM 0xffffffffu

__device__ __forceinline__ int refl(int i) {
    i = (i < 0) ? -i : i;
    return (i >= IN) ? (2 * IN - 2 - i) : i;
}

__device__ __forceinline__ float fmax4(float a, float b, float c, float d) {
    return fmaxf(fmaxf(a, b), fmaxf(c, d));
}

__device__ __forceinline__ float2 vmax2(float2 a, float2 b) {
    return make_float2(fmaxf(a.x, b.x), fmaxf(a.y, b.y));
}

// ---------------------------------------------------------------------------
// S2 level (4x4 windows) from base, VERTICAL SLIDING WINDOW:
// warp w owns 3 consecutive output rows i0..i0+2 (i0 = lo + 3w); loads the 6
// source rows once (2 loads/row amortized instead of 4), prefix/suffix maxes
// give the three vertical 4-row maxes, horizontal window of 4 via shuffles.
// DSTN odd -> last pair's 2nd element lands in padding (never read).
// ---------------------------------------------------------------------------
template <int SRCP, int SRCR, int DSTP, int DSTN>
__device__ __forceinline__ void build_s2_slide(const float* __restrict__ src,
                                               float* __restrict__ dst,
                                               int w, int l, int lo, int hi) {
    constexpr int NPAIR = (DSTN + 1) / 2;
    const int j0 = min(2 * l, SRCP - 2);
    const bool on = (l < NPAIR);
    const int i0 = lo + 3 * w;
    if (i0 <= hi) {                          // warp-uniform
        float2 r[6];
        #pragma unroll
        for (int k = 0; k < 6; k++)
            r[k] = *reinterpret_cast<const float2*>(
                src + min(i0 + k, SRCR - 1) * SRCP + j0);
        float2 t12 = vmax2(r[1], r[2]);
        float2 t34 = vmax2(r[3], r[4]);
        float2 o[3];
        o[0] = vmax2(vmax2(r[0], t12), r[3]);
        o[1] = vmax2(t12, t34);
        o[2] = vmax2(vmax2(r[2], t34), r[5]);
        #pragma unroll
        for (int k = 0; k < 3; k++) {
            if (i0 + k <= hi) {              // warp-uniform
                float mx = o[k].x, my = o[k].y;
                float nx  = __shfl_down_sync(FULLM, mx, 1);   // col j0+2
                float ny  = __shfl_down_sync(FULLM, my, 1);   // col j0+3
                float mmx = __shfl_down_sync(FULLM, mx, 2);   // col j0+4
                float v0 = fmax4(mx, my, nx, ny);
                float v1 = fmax4(my, nx, ny, mmx);
                if (on)
                    *reinterpret_cast<float2*>(dst + (i0 + k) * DSTP + 2 * l) =
                        make_float2(v0, v1);
            }
        }
    }
}

// S3 from S2 (vertical span 4): dst[i][j] = max src{i,i+4}x{j,j+4}
template <int SRCP, int DSTP, int DSTN>
__device__ __forceinline__ void build_s4(const float* __restrict__ src,
                                         float* __restrict__ dst,
                                         int w, int l, int lo, int hi) {
    constexpr int NPAIR = (DSTN + 1) / 2;
    const int j0 = min(2 * l, SRCP - 2);
    const bool on = (l < NPAIR);
    for (int i = lo + w; i <= hi; i += 16) {
        float2 a = *reinterpret_cast<const float2*>(src + i * SRCP + j0);
        float2 b = *reinterpret_cast<const float2*>(src + (i + 4) * SRCP + j0);
        float mx = fmaxf(a.x, b.x);
        float my = fmaxf(a.y, b.y);
        float bx = __shfl_down_sync(FULLM, mx, 2);    // col j0+4
        float by = __shfl_down_sync(FULLM, my, 2);    // col j0+5
        if (on)
            *reinterpret_cast<float2*>(dst + i * DSTP + 2 * l) =
                make_float2(fmaxf(mx, bx), fmaxf(my, by));
    }
}

// ---------------------------------------------------------------------------
// smem layout (floats):
//  sEE  : 46 x 46 = 2116 @ 0      sS2E : 43 x 44 = 1892 @ 2116
//  sS3E : 39 x 40 = 1560 @ 4008   sOO  : 42 x 42 = 1764 @ 5568
//  sS2O : 39 x 40 = 1560 @ 7332   sS3O : 35 x 36 = 1260 @ 8892
//  total 10152 floats = 40608 B -> 4 blocks/SM @ 512 thr
// ---------------------------------------------------------------------------
__global__ __launch_bounds__(512, 4) void fused_pool(const float* __restrict__ x,
                                                     float* __restrict__ out) {
    __shared__ __align__(16) float sm[10152];
    float* sEE  = sm;
    float* sS2E = sm + 2116;
    float* sS3E = sm + 4008;
    float* sOO  = sm + 5568;
    float* sS2O = sm + 7332;
    float* sS3O = sm + 8892;

    const int p   = blockIdx.z;
    const int ty0 = blockIdx.y * 32;
    const int tx0 = blockIdx.x * 32;
    const int tid = threadIdx.x;
    const int w   = tid >> 5;
    const int l   = tid & 31;

    // Column extremes of |dx| over this tile (block-uniform)
    int dxl = tx0 - 112, dxh = tx0 + 31 - 112;
    int dxmin = (dxl > 0) ? dxl : ((dxh < 0) ? -dxh : 0);
    int dxmax = max(abs(dxl), abs(dxh));
    int dxmin2 = dxmin * dxmin, dxmax2 = dxmax * dxmax;

    // Per-zone row ranges via one ballot per zone (lane = tile row)
    int l2 = 127, h2 = -1, l8 = 127, h8 = -1, l14 = 127, h14 = -1;
    int l20 = 127, h20 = -1, l26 = 127, h26 = -1;
    {
        int dy  = ty0 + l - 112;
        int rm2 = dy * dy + dxmin2;
        int rM2 = dy * dy + dxmax2;
        unsigned m;
        m = __ballot_sync(FULLM, rm2 < 3600);
        if (m) { l2  = __ffs(m) - 1; h2  = 31 - __clz(m); }
        m = __ballot_sync(FULLM, rm2 < 5625  && rM2 >= 3600);
        if (m) { l8  = __ffs(m) - 1; h8  = 31 - __clz(m); }
        m = __ballot_sync(FULLM, rm2 < 8100  && rM2 >= 5625);
        if (m) { l14 = __ffs(m) - 1; h14 = 31 - __clz(m); }
        m = __ballot_sync(FULLM, rm2 < 11025 && rM2 >= 8100);
        if (m) { l20 = __ffs(m) - 1; h20 = 31 - __clz(m); }
        m = __ballot_sync(FULLM, rM2 >= 11025);
        if (m) { l26 = __ffs(m) - 1; h26 = 31 - __clz(m); }
    }

    // Producer row ranges from consumer needs
    int s3eLo = 127, s3eHi = -1;
    if (h26 >= 0) { s3eLo = l26 + 1; s3eHi = h26 + 6; }
    int s2eLo = 127, s2eHi = -1;
    if (h14 >= 0) { s2eLo = l14 + 4; s2eHi = h14 + 7; }
    if (s3eHi >= 0) { s2eLo = min(s2eLo, s3eLo); s2eHi = max(s2eHi, s3eHi + 4); }
    s2eHi = min(s2eHi, 42);
    int eeLo = 127, eeHi = -1;
    if (h2 >= 0) { eeLo = l2 + 7; eeHi = h2 + 7; }
    if (s2eHi >= 0) { eeLo = min(eeLo, s2eLo); eeHi = max(eeHi, s2eHi + 3); }
    eeHi = min(eeHi, 45);
    s3eHi = min(s3eHi, 38);

    int s3oLo = 127, s3oHi = -1;
    if (h20 >= 0) { s3oLo = l20; s3oHi = h20 + 2; }
    int s2oLo = 127, s2oHi = -1;
    if (h8 >= 0) { s2oLo = l8 + 3; s2oHi = h8 + 3; }
    if (s3oHi >= 0) { s2oLo = min(s2oLo, s3oLo); s2oHi = max(s2oHi, s3oHi + 4); }
    s2oHi = min(s2oHi, 38);
    int ooLo = 127, ooHi = -1;
    if (s2oHi >= 0) { ooLo = s2oLo; ooHi = min(s2oHi + 3, 41); }
    s3oHi = min(s3oHi, 34);

    const float* in = x + (size_t)p * IN * IN;
    const float NEG_INF = __int_as_float(0xff800000);
    const bool xInt = (tx0 >= 32) && (tx0 <= 160);   // block-uniform

    // ---- Stage EE rows [eeLo,eeHi]:
    //   sEE[i][j] = max input rows {2yp,2yp+1} cols {2xp,2xp+1},
    //   yp = ty0-7+i, xp = tx0-7+j.
    if (xInt) {
        // Fast path: one aligned LDG.128 per lane per input row.
        // Lane l covers input cols cb..cb+3, cb = 2*tx0-16+4l (16B aligned).
        // Pair j0=2l needs cols cb+2,cb+3 (own .z,.w) and next lane's .x,.y.
        const int cb = 2 * tx0 - 16 + 4 * l;
        for (int i = eeLo + w; i <= eeHi; i += 16) {
            int yp = ty0 - 7 + i;
            int r0, r1;
            if ((unsigned)yp < 224u) { r0 = 2 * yp; r1 = 2 * yp + 1; }
            else                     { r0 = refl(2 * yp); r1 = refl(2 * yp + 1); }
            float4 A = *reinterpret_cast<const float4*>(in + (size_t)r0 * IN + cb);
            float4 B = *reinterpret_cast<const float4*>(in + (size_t)r1 * IN + cb);
            float mzw = fmax4(A.z, A.w, B.z, B.w);
            float mxy = fmax4(A.x, A.y, B.x, B.y);
            float v1 = __shfl_down_sync(FULLM, mxy, 1);
            if (l < 23)
                *reinterpret_cast<float2*>(sEE + i * 46 + 2 * l) =
                    make_float2(mzw, v1);
        }
    } else if (l < 23) {
        const int j0 = 2 * l;
        for (int i = eeLo + w; i <= eeHi; i += 16) {
            int yp = ty0 - 7 + i;
            int r0, r1;
            if ((unsigned)yp < 224u) { r0 = 2 * yp; r1 = 2 * yp + 1; }
            else                     { r0 = refl(2 * yp); r1 = refl(2 * yp + 1); }
            const float* R0 = in + (size_t)r0 * IN;
            const float* R1 = in + (size_t)r1 * IN;
            int xp0 = tx0 - 7 + j0;
            float v0, v1;
            if ((unsigned)xp0 < 223u) {
                float2 a = *reinterpret_cast<const float2*>(R0 + 2 * xp0);
                float2 b = *reinterpret_cast<const float2*>(R0 + 2 * xp0 + 2);
                float2 c = *reinterpret_cast<const float2*>(R1 + 2 * xp0);
                float2 d = *reinterpret_cast<const float2*>(R1 + 2 * xp0 + 2);
                v0 = fmax4(a.x, a.y, c.x, c.y);
                v1 = fmax4(b.x, b.y, d.x, d.y);
            } else {
                int c0 = refl(2 * xp0),     c1 = refl(2 * xp0 + 1);
                v0 = fmax4(R0[c0], R0[c1], R1[c0], R1[c1]);
                int c2 = refl(2 * xp0 + 2), c3 = refl(2 * xp0 + 3);
                v1 = fmax4(R0[c2], R0[c3], R1[c2], R1[c3]);
            }
            *reinterpret_cast<float2*>(sEE + i * 46 + j0) = make_float2(v0, v1);
        }
    }

    // ---- Stage OO rows [ooLo,ooHi]:
    //   sOO[i][j] = max rows {2gy+1,2gy+2} cols {2gx+1,2gx+2},
    //   gy = ty0-5+i, gx = tx0-5+j; -inf outside [0,223].
    if (xInt) {
        // Lane l covers cols cb..cb+3, cb = 2*tx0-12+4l (16B aligned).
        // Pair j0=2l: v0 = max(own .w, next .x); v1 = max(next .y, next .z).
        const int cb = 2 * tx0 - 12 + 4 * l;
        for (int i = ooLo + w; i <= ooHi; i += 16) {
            int gy = ty0 - 5 + i;
            float v0 = NEG_INF, v1 = NEG_INF;
            if ((unsigned)gy < 224u) {        // warp-uniform
                int r0 = 2 * gy + 1;
                int r1 = (gy == 223) ? 446 : 2 * gy + 2;
                float4 A = *reinterpret_cast<const float4*>(in + (size_t)r0 * IN + cb);
                float4 B = *reinterpret_cast<const float4*>(in + (size_t)r1 * IN + cb);
                float mw = fmaxf(A.w, B.w);
                float mx = fmaxf(A.x, B.x);
                float dyz = fmax4(A.y, A.z, B.y, B.z);
                float nx = __shfl_down_sync(FULLM, mx, 1);
                float nd = __shfl_down_sync(FULLM, dyz, 1);
                v0 = fmaxf(mw, nx);
                v1 = nd;
            }
            if (l < 21)
                *reinterpret_cast<float2*>(sOO + i * 42 + 2 * l) =
                    make_float2(v0, v1);
        }
    } else if (l < 21) {
        const int j0 = 2 * l;
        for (int i = ooLo + w; i <= ooHi; i += 16) {
            int gy = ty0 - 5 + i;
            float v0 = NEG_INF, v1 = NEG_INF;
            if ((unsigned)gy < 224u) {
                int r0 = 2 * gy + 1;
                int r1 = (gy == 223) ? 446 : 2 * gy + 2;
                const float* R0 = in + (size_t)r0 * IN;
                const float* R1 = in + (size_t)r1 * IN;
                int gx0 = tx0 - 5 + j0;
                if ((unsigned)gx0 < 224u) {
                    int c0 = 2 * gx0 + 1;
                    int c1 = (gx0 == 223) ? 446 : 2 * gx0 + 2;
                    v0 = fmax4(R0[c0], R0[c1], R1[c0], R1[c1]);
                }
                int gx1 = gx0 + 1;
                if ((unsigned)gx1 < 224u) {
                    int c0 = 2 * gx1 + 1;
                    int c1 = (gx1 == 223) ? 446 : 2 * gx1 + 2;
                    v1 = fmax4(R0[c0], R0[c1], R1[c0], R1[c1]);
                }
            }
            *reinterpret_cast<float2*>(sOO + i * 42 + j0) = make_float2(v0, v1);
        }
    }
    __syncthreads();

    // ---- Level-2 tables (4x4 windows), sliding vertical window
    build_s2_slide<46, 46, 44, 43>(sEE, sS2E, w, l, s2eLo, s2eHi);
    build_s2_slide<42, 42, 40, 39>(sOO, sS2O, w, l, s2oLo, s2oHi);
    __syncthreads();

    // ---- Level-3 tables (8x8 windows)
    build_s4<44, 40, 39>(sS2E, sS3E, w, l, s3eLo, s3eHi);
    build_s4<40, 36, 35>(sS2O, sS3O, w, l, s3oLo, s3oHi);
    __syncthreads();

    // ---- Queries: 2 output pixels per thread
    #pragma unroll
    for (int q = 0; q < 2; q++) {
        int ry = w + q * 16;
        int rx = l;
        int oy = ty0 + ry, ox = tx0 + rx;
        int dy = oy - 112, dx = ox - 112;
        int d2 = dy * dy + dx * dx;
        float v;
        if (d2 < 3600) {
            v = sEE[(ry + 7) * 46 + (rx + 7)];                       // k=2
        } else if (d2 < 5625) {
            v = sS2O[(ry + 3) * 40 + (rx + 3)];                      // k=8
        } else if (d2 < 8100) {
            const float* b = sS2E + (ry + 4) * 44 + (rx + 4);        // k=14
            v = fmax4(b[0], b[3], b[3 * 44], b[3 * 44 + 3]);
        } else if (d2 < 11025) {
            const float* b = sS3O + ry * 36 + rx;                    // k=20
            v = fmax4(b[0], b[2], b[2 * 36], b[2 * 36 + 2]);
        } else {
            const float* b = sS3E + (ry + 1) * 40 + (rx + 1);        // k=26
            v = fmax4(b[0], b[5], b[5 * 40], b[5 * 40 + 5]);
        }
        out[((size_t)p * OUT + oy) * OUT + ox] = v;
    }
}

extern "C" void kernel_launch(void* const* d_in, const int* in_sizes, int n_in,
                              void* d_out, int out_size) {
    const float* x = (const float*)d_in[0];
    float* out = (float*)d_out;
    fused_pool<<<dim3(7, 7, NP), 512>>>(x, out);
}

// round 9
// speedup vs baseline: 2.1027x; 1.0590x over previous
#include <cuda_runtime.h>

#define IN 448
#define OUT 224
#define NP 512          // 8*64 planes
#define FULLM 0xffffffffu

__device__ __forceinline__ int refl(int i) {
    i = (i < 0) ? -i : i;
    return (i >= IN) ? (2 * IN - 2 - i) : i;
}

__device__ __forceinline__ float fmax4(float a, float b, float c, float d) {
    return fmaxf(fmaxf(a, b), fmaxf(c, d));
}

__device__ __forceinline__ float2 vmax2(float2 a, float2 b) {
    return make_float2(fmaxf(a.x, b.x), fmaxf(a.y, b.y));
}

// ---------------------------------------------------------------------------
// S2 (4x4 windows) from base, single-pass: warp w owns 3 consecutive output
// rows i0..i0+2 (i0 = lo+3w; 16 warps x 3 = 48 rows covers any range).
// 6 source rows loaded once at immediate offsets from one base. Overshoot
// rows (> hi) are written unconditionally into pad rows (never read); valid
// outputs only touch valid source rows (consumer-range invariant).
// Write guard is on the DEST pitch: pairs up to col DSTP-1 (valid + pad col).
// ---------------------------------------------------------------------------
template <int SRCP, int DSTP>
__device__ __forceinline__ void build_s2_slide(const float* __restrict__ src,
                                               float* __restrict__ dst,
                                               int w, int l, int lo, int hi) {
    const int j0 = min(2 * l, SRCP - 2);
    const bool on = (2 * l + 2 <= DSTP);     // stay inside dest pitch
    const int i0 = lo + 3 * w;
    if (i0 <= hi) {                          // warp-uniform
        const float* s = src + i0 * SRCP + j0;
        float2 r[6];
        #pragma unroll
        for (int k = 0; k < 6; k++)
            r[k] = *reinterpret_cast<const float2*>(s + k * SRCP);
        float2 t12 = vmax2(r[1], r[2]);
        float2 t34 = vmax2(r[3], r[4]);
        float2 o[3];
        o[0] = vmax2(vmax2(r[0], t12), r[3]);
        o[1] = vmax2(t12, t34);
        o[2] = vmax2(vmax2(r[2], t34), r[5]);
        float* d = dst + i0 * DSTP + 2 * l;
        #pragma unroll
        for (int k = 0; k < 3; k++) {
            float mx = o[k].x, my = o[k].y;
            float nx  = __shfl_down_sync(FULLM, mx, 1);   // col j0+2
            float ny  = __shfl_down_sync(FULLM, my, 1);   // col j0+3
            float mmx = __shfl_down_sync(FULLM, mx, 2);   // col j0+4
            if (on)
                *reinterpret_cast<float2*>(d + k * DSTP) =
                    make_float2(fmax4(mx, my, nx, ny), fmax4(my, nx, ny, mmx));
        }
    }
}

// S3 from S2 (vertical span 4), single-pass 3 rows/warp.
template <int SRCP, int DSTP>
__device__ __forceinline__ void build_s4(const float* __restrict__ src,
                                         float* __restrict__ dst,
                                         int w, int l, int lo, int hi) {
    const int j0 = min(2 * l, SRCP - 2);
    const bool on = (2 * l + 2 <= DSTP);     // stay inside dest pitch
    const int i0 = lo + 3 * w;
    if (i0 <= hi) {                          // warp-uniform
        const float* s = src + i0 * SRCP + j0;
        float* d = dst + i0 * DSTP + 2 * l;
        #pragma unroll
        for (int k = 0; k < 3; k++) {
            float2 a = *reinterpret_cast<const float2*>(s + k * SRCP);
            float2 b = *reinterpret_cast<const float2*>(s + (k + 4) * SRCP);
            float mx = fmaxf(a.x, b.x);
            float my = fmaxf(a.y, b.y);
            float bx = __shfl_down_sync(FULLM, mx, 2);    // col j0+4
            float by = __shfl_down_sync(FULLM, my, 2);    // col j0+5
            if (on)
                *reinterpret_cast<float2*>(d + k * DSTP) =
                    make_float2(fmaxf(mx, bx), fmaxf(my, by));
        }
    }
}

// ---------------------------------------------------------------------------
// smem layout (floats), padded rows absorb single-pass overshoot:
//  sEE  : 48 x 46 = 2208 @ 0     (valid rows 0..45, cols 0..45)
//  sS2E : 45 x 44 = 1980 @ 2208  (valid rows 0..42, cols 0..42, col 43 pad)
//  sS3E : 41 x 40 = 1640 @ 4188  (valid rows 0..38, cols 0..38, col 39 pad)
//  sOO  : 44 x 42 = 1848 @ 5828  (valid rows 0..41, cols 0..41)
//  sS2O : 41 x 40 = 1640 @ 7676  (valid rows 0..38, cols 0..38, col 39 pad)
//  sS3O : 37 x 36 = 1332 @ 9316  (valid rows 0..34, cols 0..34, col 35 pad)
//  total 10648 floats = 42592 B -> 4 blocks/SM @ 512 thr
// ---------------------------------------------------------------------------
__global__ __launch_bounds__(512, 4) void fused_pool(const float* __restrict__ x,
                                                     float* __restrict__ out) {
    __shared__ __align__(16) float sm[10648];
    float* sEE  = sm;
    float* sS2E = sm + 2208;
    float* sS3E = sm + 4188;
    float* sOO  = sm + 5828;
    float* sS2O = sm + 7676;
    float* sS3O = sm + 9316;

    const int p   = blockIdx.z;
    const int ty0 = blockIdx.y * 32;
    const int tx0 = blockIdx.x * 32;
    const int tid = threadIdx.x;
    const int w   = tid >> 5;
    const int l   = tid & 31;

    // Column extremes of |dx| over this tile (block-uniform)
    int dxl = tx0 - 112, dxh = tx0 + 31 - 112;
    int dxmin = (dxl > 0) ? dxl : ((dxh < 0) ? -dxh : 0);
    int dxmax = max(abs(dxl), abs(dxh));
    int dxmin2 = dxmin * dxmin, dxmax2 = dxmax * dxmax;

    // Per-zone row ranges via one ballot per zone (lane = tile row)
    int l2 = 127, h2 = -1, l8 = 127, h8 = -1, l14 = 127, h14 = -1;
    int l20 = 127, h20 = -1, l26 = 127, h26 = -1;
    {
        int dy  = ty0 + l - 112;
        int rm2 = dy * dy + dxmin2;
        int rM2 = dy * dy + dxmax2;
        unsigned m;
        m = __ballot_sync(FULLM, rm2 < 3600);
        if (m) { l2  = __ffs(m) - 1; h2  = 31 - __clz(m); }
        m = __ballot_sync(FULLM, rm2 < 5625  && rM2 >= 3600);
        if (m) { l8  = __ffs(m) - 1; h8  = 31 - __clz(m); }
        m = __ballot_sync(FULLM, rm2 < 8100  && rM2 >= 5625);
        if (m) { l14 = __ffs(m) - 1; h14 = 31 - __clz(m); }
        m = __ballot_sync(FULLM, rm2 < 11025 && rM2 >= 8100);
        if (m) { l20 = __ffs(m) - 1; h20 = 31 - __clz(m); }
        m = __ballot_sync(FULLM, rM2 >= 11025);
        if (m) { l26 = __ffs(m) - 1; h26 = 31 - __clz(m); }
    }

    // Producer row ranges from consumer needs
    int s3eLo = 127, s3eHi = -1;
    if (h26 >= 0) { s3eLo = l26 + 1; s3eHi = h26 + 6; }
    int s2eLo = 127, s2eHi = -1;
    if (h14 >= 0) { s2eLo = l14 + 4; s2eHi = h14 + 7; }
    if (s3eHi >= 0) { s2eLo = min(s2eLo, s3eLo); s2eHi = max(s2eHi, s3eHi + 4); }
    s2eHi = min(s2eHi, 42);
    int eeLo = 127, eeHi = -1;
    if (h2 >= 0) { eeLo = l2 + 7; eeHi = h2 + 7; }
    if (s2eHi >= 0) { eeLo = min(eeLo, s2eLo); eeHi = max(eeHi, s2eHi + 3); }
    eeHi = min(eeHi, 45);
    s3eHi = min(s3eHi, 38);

    int s3oLo = 127, s3oHi = -1;
    if (h20 >= 0) { s3oLo = l20; s3oHi = h20 + 2; }
    int s2oLo = 127, s2oHi = -1;
    if (h8 >= 0) { s2oLo = l8 + 3; s2oHi = h8 + 3; }
    if (s3oHi >= 0) { s2oLo = min(s2oLo, s3oLo); s2oHi = max(s2oHi, s3oHi + 4); }
    s2oHi = min(s2oHi, 38);
    int ooLo = 127, ooHi = -1;
    if (s2oHi >= 0) { ooLo = s2oLo; ooHi = min(s2oHi + 3, 41); }
    s3oHi = min(s3oHi, 34);

    const float* in = x + p * (IN * IN);
    const float NEG_INF = __int_as_float(0xff800000);
    const bool xInt = (tx0 >= 32) && (tx0 <= 160);
    const bool yInt = (ty0 >= 32) && (ty0 <= 160);

    if (xInt && yInt) {
        // ================= INTERIOR FAST PATH (no reflection anywhere) ======
        {
            const int i0 = eeLo + 3 * w;
            if (i0 <= eeHi) {                              // warp-uniform
                const int cb = 2 * tx0 - 16 + 4 * l;       // 16B-aligned
                const float* P = in + (2 * (ty0 - 7 + i0)) * IN + cb;
                float* d = sEE + i0 * 46 + 2 * l;
                #pragma unroll
                for (int k = 0; k < 3; k++) {
                    float4 A = *reinterpret_cast<const float4*>(P + (2 * k) * IN);
                    float4 B = *reinterpret_cast<const float4*>(P + (2 * k + 1) * IN);
                    float mzw = fmax4(A.z, A.w, B.z, B.w);
                    float mxy = fmax4(A.x, A.y, B.x, B.y);
                    float v1 = __shfl_down_sync(FULLM, mxy, 1);
                    if (l < 23)
                        *reinterpret_cast<float2*>(d + k * 46) =
                            make_float2(mzw, v1);
                }
            }
        }
        {
            const int i0 = ooLo + 3 * w;
            if (i0 <= ooHi) {                              // warp-uniform
                const int cb = 2 * tx0 - 12 + 4 * l;       // 16B-aligned
                const float* P = in + (2 * (ty0 - 5 + i0) + 1) * IN + cb;
                float* d = sOO + i0 * 42 + 2 * l;
                #pragma unroll
                for (int k = 0; k < 3; k++) {
                    float4 A = *reinterpret_cast<const float4*>(P + (2 * k) * IN);
                    float4 B = *reinterpret_cast<const float4*>(P + (2 * k + 1) * IN);
                    float mw  = fmaxf(A.w, B.w);
                    float mx  = fmaxf(A.x, B.x);
                    float dyz = fmax4(A.y, A.z, B.y, B.z);
                    float nx = __shfl_down_sync(FULLM, mx, 1);
                    float nd = __shfl_down_sync(FULLM, dyz, 1);
                    if (l < 21)
                        *reinterpret_cast<float2*>(d + k * 42) =
                            make_float2(fmaxf(mw, nx), nd);
                }
            }
        }
    } else {
        // ================= GENERAL PATH (border tiles) =====================
        if (xInt) {
            const int cb = 2 * tx0 - 16 + 4 * l;
            for (int i = eeLo + w; i <= eeHi; i += 16) {
                int yp = ty0 - 7 + i;
                int r0, r1;
                if ((unsigned)yp < 224u) { r0 = 2 * yp; r1 = 2 * yp + 1; }
                else                     { r0 = refl(2 * yp); r1 = refl(2 * yp + 1); }
                float4 A = *reinterpret_cast<const float4*>(in + r0 * IN + cb);
                float4 B = *reinterpret_cast<const float4*>(in + r1 * IN + cb);
                float mzw = fmax4(A.z, A.w, B.z, B.w);
                float mxy = fmax4(A.x, A.y, B.x, B.y);
                float v1 = __shfl_down_sync(FULLM, mxy, 1);
                if (l < 23)
                    *reinterpret_cast<float2*>(sEE + i * 46 + 2 * l) =
                        make_float2(mzw, v1);
            }
        } else if (l < 23) {
            const int j0 = 2 * l;
            for (int i = eeLo + w; i <= eeHi; i += 16) {
                int yp = ty0 - 7 + i;
                int r0, r1;
                if ((unsigned)yp < 224u) { r0 = 2 * yp; r1 = 2 * yp + 1; }
                else                     { r0 = refl(2 * yp); r1 = refl(2 * yp + 1); }
                const float* R0 = in + r0 * IN;
                const float* R1 = in + r1 * IN;
                int xp0 = tx0 - 7 + j0;
                float v0, v1;
                if ((unsigned)xp0 < 223u) {
                    float2 a = *reinterpret_cast<const float2*>(R0 + 2 * xp0);
                    float2 b = *reinterpret_cast<const float2*>(R0 + 2 * xp0 + 2);
                    float2 c = *reinterpret_cast<const float2*>(R1 + 2 * xp0);
                    float2 d = *reinterpret_cast<const float2*>(R1 + 2 * xp0 + 2);
                    v0 = fmax4(a.x, a.y, c.x, c.y);
                    v1 = fmax4(b.x, b.y, d.x, d.y);
                } else {
                    int c0 = refl(2 * xp0),     c1 = refl(2 * xp0 + 1);
                    v0 = fmax4(R0[c0], R0[c1], R1[c0], R1[c1]);
                    int c2 = refl(2 * xp0 + 2), c3 = refl(2 * xp0 + 3);
                    v1 = fmax4(R0[c2], R0[c3], R1[c2], R1[c3]);
                }
                *reinterpret_cast<float2*>(sEE + i * 46 + j0) = make_float2(v0, v1);
            }
        }

        if (xInt) {
            const int cb = 2 * tx0 - 12 + 4 * l;
            for (int i = ooLo + w; i <= ooHi; i += 16) {
                int gy = ty0 - 5 + i;
                float v0 = NEG_INF, v1 = NEG_INF;
                if ((unsigned)gy < 224u) {        // warp-uniform
                    int r0 = 2 * gy + 1;
                    int r1 = (gy == 223) ? 446 : 2 * gy + 2;
                    float4 A = *reinterpret_cast<const float4*>(in + r0 * IN + cb);
                    float4 B = *reinterpret_cast<const float4*>(in + r1 * IN + cb);
                    float mw  = fmaxf(A.w, B.w);
                    float mx  = fmaxf(A.x, B.x);
                    float dyz = fmax4(A.y, A.z, B.y, B.z);
                    float nx = __shfl_down_sync(FULLM, mx, 1);
                    float nd = __shfl_down_sync(FULLM, dyz, 1);
                    v0 = fmaxf(mw, nx);
                    v1 = nd;
                }
                if (l < 21)
                    *reinterpret_cast<float2*>(sOO + i * 42 + 2 * l) =
                        make_float2(v0, v1);
            }
        } else if (l < 21) {
            const int j0 = 2 * l;
            for (int i = ooLo + w; i <= ooHi; i += 16) {
                int gy = ty0 - 5 + i;
                float v0 = NEG_INF, v1 = NEG_INF;
                if ((unsigned)gy < 224u) {
                    int r0 = 2 * gy + 1;
                    int r1 = (gy == 223) ? 446 : 2 * gy + 2;
                    const float* R0 = in + r0 * IN;
                    const float* R1 = in + r1 * IN;
                    int gx0 = tx0 - 5 + j0;
                    if ((unsigned)gx0 < 224u) {
                        int c0 = 2 * gx0 + 1;
                        int c1 = (gx0 == 223) ? 446 : 2 * gx0 + 2;
                        v0 = fmax4(R0[c0], R0[c1], R1[c0], R1[c1]);
                    }
                    int gx1 = gx0 + 1;
                    if ((unsigned)gx1 < 224u) {
                        int c0 = 2 * gx1 + 1;
                        int c1 = (gx1 == 223) ? 446 : 2 * gx1 + 2;
                        v1 = fmax4(R0[c0], R0[c1], R1[c0], R1[c1]);
                    }
                }
                *reinterpret_cast<float2*>(sOO + i * 42 + j0) = make_float2(v0, v1);
            }
        }
    }
    __syncthreads();

    // ---- Level-2 tables (4x4 windows)
    build_s2_slide<46, 44>(sEE, sS2E, w, l, s2eLo, s2eHi);
    build_s2_slide<42, 40>(sOO, sS2O, w, l, s2oLo, s2oHi);
    __syncthreads();

    // ---- Level-3 tables (8x8 windows)
    build_s4<44, 40>(sS2E, sS3E, w, l, s3eLo, s3eHi);
    build_s4<40, 36>(sS2O, sS3O, w, l, s3oLo, s3oHi);
    __syncthreads();

    // ---- Queries: 2 output pixels per thread
    #pragma unroll
    for (int q = 0; q < 2; q++) {
        int ry = w + q * 16;
        int rx = l;
        int oy = ty0 + ry, ox = tx0 + rx;
        int dy = oy - 112, dx = ox - 112;
        int d2 = dy * dy + dx * dx;
        float v;
        if (d2 < 3600) {
            v = sEE[(ry + 7) * 46 + (rx + 7)];                       // k=2
        } else if (d2 < 5625) {
            v = sS2O[(ry + 3) * 40 + (rx + 3)];                      // k=8
        } else if (d2 < 8100) {
            const float* b = sS2E + (ry + 4) * 44 + (rx + 4);        // k=14
            v = fmax4(b[0], b[3], b[3 * 44], b[3 * 44 + 3]);
        } else if (d2 < 11025) {
            const float* b = sS3O + ry * 36 + rx;                    // k=20
            v = fmax4(b[0], b[2], b[2 * 36], b[2 * 36 + 2]);
        } else {
            const float* b = sS3E + (ry + 1) * 40 + (rx + 1);        // k=26
            v = fmax4(b[0], b[5], b[5 * 40], b[5 * 40 + 5]);
        }
        out[(p * OUT + oy) * OUT + ox] = v;
    }
}

extern "C" void kernel_launch(void* const* d_in, const int* in_sizes, int n_in,
                              void* d_out, int out_size) {
    const float* x = (const float*)d_in[0];
    float* out = (float*)d_out;
    fused_pool<<<dim3(7, 7, NP), 512>>>(x, out);
}